// round 1
// baseline (speedup 1.0000x reference)
#include <cuda_runtime.h>
#include <math.h>

#define Bc 8
#define Sc 2048
#define Dc 1024
#define Ec 8
#define Kc 2
#define SUBD 128
#define SUBH 512
#define SD (Sc*Dc)          // 2097152
#define NCHUNK 256
#define CHUNK (SD/NCHUNK)   // 8192

// ---- scratch (static device globals; no runtime allocation) ----
__device__ float g_h1[Bc*Kc*Sc*SUBH];          // gelu(x_e @ w1 + b1), per (b,k)
__device__ float g_gsel[(long)Bc*Sc*Kc*SUBH];  // [b][s][k*512+c] = gelu(h1 @ w2 + b2)
__device__ float g_part[NCHUNK*Bc*Ec];         // routing partial sums
__device__ int   g_sel[Bc*Kc];                 // selected expert ids per batch

__device__ __forceinline__ float gelu_exact(float v) {
    return 0.5f * v * (1.0f + erff(v * 0.70710678118654752440f));
}

// ============================================================
// Routing stage 1: per-chunk partial dot products, deterministic
// grid = NCHUNK blocks x 256 threads
// ============================================================
__global__ void route_partial_kernel(const float* __restrict__ x,
                                     const float* __restrict__ w) {
    const int chunk = blockIdx.x;
    const int tid   = threadIdx.x;

    float acc[Bc][Ec];
#pragma unroll
    for (int b = 0; b < Bc; b++)
#pragma unroll
        for (int e = 0; e < Ec; e++) acc[b][e] = 0.f;

    const long base = (long)chunk * CHUNK;
    for (int it = 0; it < CHUNK / 256; it++) {
        const long i = base + it * 256 + tid;
        const float4 w0 = *(const float4*)(w + i * 8);
        const float4 w1v = *(const float4*)(w + i * 8 + 4);
        const float wv[8] = {w0.x, w0.y, w0.z, w0.w, w1v.x, w1v.y, w1v.z, w1v.w};
#pragma unroll
        for (int b = 0; b < Bc; b++) {
            const float xv = x[(long)b * SD + i];
#pragma unroll
            for (int e = 0; e < Ec; e++) acc[b][e] = fmaf(xv, wv[e], acc[b][e]);
        }
    }

    __shared__ float sm[8][64];
    const int lane = tid & 31, warp = tid >> 5;
#pragma unroll
    for (int b = 0; b < Bc; b++) {
#pragma unroll
        for (int e = 0; e < Ec; e++) {
            float v = acc[b][e];
#pragma unroll
            for (int o = 16; o > 0; o >>= 1) v += __shfl_down_sync(0xffffffffu, v, o);
            if (lane == 0) sm[warp][b * 8 + e] = v;
        }
    }
    __syncthreads();
    if (tid < 64) {
        float s = 0.f;
#pragma unroll
        for (int w2 = 0; w2 < 8; w2++) s += sm[w2][tid];
        g_part[chunk * 64 + tid] = s;   // index = b*8+e
    }
}

// ============================================================
// Routing stage 2: reduce chunks (fixed order), top-2 per batch
// 1 block x 64 threads
// ============================================================
__global__ void route_topk_kernel(const float* __restrict__ b_switch) {
    __shared__ float lg[64];
    const int t = threadIdx.x;   // t = b*8+e
    float s = b_switch[t & 7];
    for (int c = 0; c < NCHUNK; c++) s += g_part[c * 64 + t];
    lg[t] = s;
    __syncthreads();
    if (t < Bc) {
        const float* L = lg + t * 8;
        int i0 = 0; float v0 = L[0];
#pragma unroll
        for (int e = 1; e < 8; e++) if (L[e] > v0) { v0 = L[e]; i0 = e; }
        int i1 = -1; float v1 = -3.0e38f;
#pragma unroll
        for (int e = 0; e < 8; e++) if (e != i0 && L[e] > v1) { v1 = L[e]; i1 = e; }
        g_sel[t * 2 + 0] = i0;
        g_sel[t * 2 + 1] = i1;
    }
}

// ============================================================
// Tiled fp32 GEMM, 128x128x8 block tile, 8x8 microtile, 256 thr
// MODE 0: h1 = gelu(x[:, e*128:+128] @ w1[e] + b1[e])        (K=128)
// MODE 1: g  = gelu(h1 @ w2[e] + b2[e])                      (K=512)
// MODE 2: out = g_cat @ gather(w_out) + b_out                (K=1024)
// ============================================================
template <int MODE, bool DO_GELU>
__global__ void __launch_bounds__(256, 2)
gemm_kernel(const float* __restrict__ A0, const float* __restrict__ B0,
            const float* __restrict__ bias0, float* __restrict__ C0) {
    constexpr int BM = 128, BN = 128, BK = 8, TM = 8, TN = 8;
    __shared__ float As[BK][BM];
    __shared__ float Bs[BK][BN];

    const int z   = blockIdx.z;
    const int tid = threadIdx.x;
    const int tx  = tid & 15, ty = tid >> 4;
    const int rowBlock = blockIdx.y * BM;
    const int colBlock = blockIdx.x * BN;

    const float* A; const float* bias; float* C;
    int lda, ldc, Kdim;
    int e0 = 0, e1 = 0;
    const float* Bbase = B0;

    if (MODE == 0) {
        const int e = g_sel[z];
        A = A0 + (long)(z >> 1) * SD + e * SUBD; lda = Dc; Kdim = SUBD;
        Bbase = B0 + (long)e * SUBD * SUBH;
        bias = bias0 + e * SUBH;
        C = g_h1 + (long)z * Sc * SUBH; ldc = SUBH;
    } else if (MODE == 1) {
        const int e = g_sel[z];
        A = g_h1 + (long)z * Sc * SUBH; lda = SUBH; Kdim = SUBH;
        Bbase = B0 + (long)e * SUBH * SUBH;
        bias = bias0 + e * SUBH;
        C = g_gsel + (long)(z >> 1) * Sc * (Kc * SUBH) + (z & 1) * SUBH; ldc = Kc * SUBH;
    } else {
        A = g_gsel + (long)z * Sc * (Kc * SUBH); lda = Kc * SUBH; Kdim = Kc * SUBH;
        bias = bias0;
        C = C0 + (long)z * Sc * Dc; ldc = Dc;
        e0 = g_sel[z * 2]; e1 = g_sel[z * 2 + 1];
    }

    float acc[TM][TN];
#pragma unroll
    for (int i = 0; i < TM; i++)
#pragma unroll
        for (int j = 0; j < TN; j++) acc[i][j] = 0.f;

    const int arow = tid >> 1, acol = (tid & 1) * 4;   // A tile: 128 rows x 8 k
    const int brow = tid >> 5, bcol = (tid & 31) * 4;  // B tile: 8 k x 128 cols

    for (int k0 = 0; k0 < Kdim; k0 += BK) {
        // load A tile (transposed into smem)
        const float4 av = *(const float4*)(A + (long)(rowBlock + arow) * lda + k0 + acol);
        As[acol + 0][arow] = av.x;
        As[acol + 1][arow] = av.y;
        As[acol + 2][arow] = av.z;
        As[acol + 3][arow] = av.w;

        // load B tile (row remap for MODE 2 expert gather)
        const int kk = k0 + brow;
        const float* Brow;
        if (MODE == 2) {
            const int r = (kk < SUBH) ? (e0 * SUBH + kk) : (e1 * SUBH + kk - SUBH);
            Brow = B0 + (long)r * Dc;
        } else {
            Brow = Bbase + (long)kk * SUBH;
        }
        *(float4*)(&Bs[brow][bcol]) = *(const float4*)(Brow + colBlock + bcol);
        __syncthreads();

#pragma unroll
        for (int k = 0; k < BK; k++) {
            float a[TM], bb[TN];
            const float4 a0 = *(const float4*)(&As[k][ty * TM]);
            const float4 a1 = *(const float4*)(&As[k][ty * TM + 4]);
            a[0]=a0.x; a[1]=a0.y; a[2]=a0.z; a[3]=a0.w;
            a[4]=a1.x; a[5]=a1.y; a[6]=a1.z; a[7]=a1.w;
            const float4 b0v = *(const float4*)(&Bs[k][tx * TN]);
            const float4 b1v = *(const float4*)(&Bs[k][tx * TN + 4]);
            bb[0]=b0v.x; bb[1]=b0v.y; bb[2]=b0v.z; bb[3]=b0v.w;
            bb[4]=b1v.x; bb[5]=b1v.y; bb[6]=b1v.z; bb[7]=b1v.w;
#pragma unroll
            for (int i = 0; i < TM; i++)
#pragma unroll
                for (int j = 0; j < TN; j++)
                    acc[i][j] = fmaf(a[i], bb[j], acc[i][j]);
        }
        __syncthreads();
    }

    // epilogue: + bias, optional gelu, vectorized store
    const int crow0 = rowBlock + ty * TM;
    const int ccol0 = colBlock + tx * TN;
    float bv[TN];
#pragma unroll
    for (int j = 0; j < TN; j++) bv[j] = bias[ccol0 + j];
#pragma unroll
    for (int i = 0; i < TM; i++) {
        float v[TN];
#pragma unroll
        for (int j = 0; j < TN; j++) {
            float t = acc[i][j] + bv[j];
            v[j] = DO_GELU ? gelu_exact(t) : t;
        }
        float* cp = C + (long)(crow0 + i) * ldc + ccol0;
        *(float4*)(cp)     = make_float4(v[0], v[1], v[2], v[3]);
        *(float4*)(cp + 4) = make_float4(v[4], v[5], v[6], v[7]);
    }
}

// ============================================================
extern "C" void kernel_launch(void* const* d_in, const int* in_sizes, int n_in,
                              void* d_out, int out_size) {
    const float* x        = (const float*)d_in[0];
    const float* w_switch = (const float*)d_in[1];
    const float* b_switch = (const float*)d_in[2];
    const float* w1       = (const float*)d_in[3];
    const float* b1       = (const float*)d_in[4];
    const float* w2       = (const float*)d_in[5];
    const float* b2       = (const float*)d_in[6];
    const float* w_out    = (const float*)d_in[7];
    const float* b_out    = (const float*)d_in[8];
    float* out = (float*)d_out;

    // 1) routing logits (deterministic two-pass reduction)
    route_partial_kernel<<<NCHUNK, 256>>>(x, w_switch);
    route_topk_kernel<<<1, 64>>>(b_switch);

    // 2) expert MLP, selected experts only (2 per batch)
    gemm_kernel<0, true><<<dim3(SUBH / 128, Sc / 128, Bc * Kc), 256>>>(x, w1, b1, nullptr);
    gemm_kernel<1, true><<<dim3(SUBH / 128, Sc / 128, Bc * Kc), 256>>>(nullptr, w2, b2, nullptr);

    // 3) output projection over gathered w_out rows
    gemm_kernel<2, false><<<dim3(Dc / 128, Sc / 128, Bc), 256>>>(nullptr, w_out, b_out, out);
}